// round 1
// baseline (speedup 1.0000x reference)
#include <cuda_runtime.h>
#include <math.h>

// ---------------- problem constants ----------------
#define Bb   8
#define Tt   2048
#define Cc   768
#define WDd  512
#define TDd  384
#define CDd  3072
#define H1h  768
#define MTOK (Bb * Tt)          // 16384

// ---------------- scratch (device globals; no allocation) ----------------
__device__ float g_xln[MTOK * Cc];        // xln, later reused as xln2
__device__ float g_x2 [MTOK * Cc];        // x after first residual, then x3 in-place
__device__ float g_h  [MTOK * CDd];       // generic GEMM output (up to 16384x3072)
__device__ float g_a  [MTOK * (CDd/2)];   // GLU output (up to 16384x1536)
__device__ float g_h1 [MTOK * TDd];
__device__ float g_h2 [MTOK * TDd];
__device__ float g_mix[Bb * TDd * Cc];
__device__ float g_s1 [Bb * (H1h/2)];
__device__ float g_s2 [Bb * (H1h/2)];
__device__ float g_ss [Bb * (CDd/2)];
__device__ float g_zero[CDd];             // zero bias (zero-initialized by CUDA)

// ---------------- LayerNorm: one block per row (C = 768) ----------------
__global__ __launch_bounds__(256) void ln_kernel(const float* __restrict__ x,
                                                 const float* __restrict__ g,
                                                 const float* __restrict__ b,
                                                 float* __restrict__ o)
{
    const int row = blockIdx.x;
    const float* xr = x + (long long)row * Cc;
    float* orow = o + (long long)row * Cc;
    const int tid = threadIdx.x;

    float v0 = xr[tid], v1 = xr[tid + 256], v2 = xr[tid + 512];
    float s = v0 + v1 + v2;
    float q = v0 * v0 + v1 * v1 + v2 * v2;

    for (int off = 16; off > 0; off >>= 1) {
        s += __shfl_down_sync(0xffffffff, s, off);
        q += __shfl_down_sync(0xffffffff, q, off);
    }
    __shared__ float ssm[8], sqm[8];
    const int wid = tid >> 5, lid = tid & 31;
    if (lid == 0) { ssm[wid] = s; sqm[wid] = q; }
    __syncthreads();
    if (tid < 8) { s = ssm[tid]; q = sqm[tid]; }
    if (wid == 0) {
        for (int off = 4; off > 0; off >>= 1) {
            s += __shfl_down_sync(0x000000ff, s, off);
            q += __shfl_down_sync(0x000000ff, q, off);
        }
        if (tid == 0) { ssm[0] = s; sqm[0] = q; }
    }
    __syncthreads();
    const float mu  = ssm[0] * (1.0f / Cc);
    const float var = sqm[0] * (1.0f / Cc) - mu * mu;
    const float rs  = rsqrtf(var + 1e-6f);

    orow[tid]       = (v0 - mu) * rs * g[tid]       + b[tid];
    orow[tid + 256] = (v1 - mu) * rs * g[tid + 256] + b[tid + 256];
    orow[tid + 512] = (v2 - mu) * rs * g[tid + 512] + b[tid + 512];
}

// ---------------- tiled SGEMM: C = A(MxK,rm) @ B(KxN,rm) + bias (+res) ----------------
// All M%128==0, N%128==0, K%8==0 here -> no bound checks.
#define BM 128
#define BN 128
#define BKT 8
#define TM 8
#define TN 8

__global__ __launch_bounds__(256) void gemm_nn(const float* __restrict__ A,
                                               const float* __restrict__ B,
                                               float* __restrict__ C,
                                               const float* __restrict__ bias,
                                               const float* __restrict__ res,
                                               int M, int N, int K,
                                               long long sA, long long sB, long long sC)
{
    __shared__ float As[BKT][BM];
    __shared__ float Bs[BKT][BN];

    const int bz = blockIdx.z;
    A += bz * sA;
    B += bz * sB;
    C += bz * sC;
    if (res) res += bz * sC;

    const int tid  = threadIdx.x;
    const int row0 = blockIdx.y * BM;
    const int col0 = blockIdx.x * BN;

    const int a_row = tid >> 1;            // 0..127
    const int a_col = (tid & 1) * 4;       // 0 or 4
    const int b_row = tid >> 5;            // 0..7
    const int b_col = (tid & 31) * 4;

    const int tx = tid & 15, ty = tid >> 4;

    float acc[TM][TN] = {};
    float ra[TM], rb[TN];

    for (int k0 = 0; k0 < K; k0 += BKT) {
        float4 av = *reinterpret_cast<const float4*>(&A[(long long)(row0 + a_row) * K + k0 + a_col]);
        As[a_col + 0][a_row] = av.x;
        As[a_col + 1][a_row] = av.y;
        As[a_col + 2][a_row] = av.z;
        As[a_col + 3][a_row] = av.w;
        *reinterpret_cast<float4*>(&Bs[b_row][b_col]) =
            *reinterpret_cast<const float4*>(&B[(long long)(k0 + b_row) * N + col0 + b_col]);
        __syncthreads();
#pragma unroll
        for (int kk = 0; kk < BKT; kk++) {
#pragma unroll
            for (int i = 0; i < TM; i++) ra[i] = As[kk][ty * TM + i];
#pragma unroll
            for (int j = 0; j < TN; j++) rb[j] = Bs[kk][tx * TN + j];
#pragma unroll
            for (int i = 0; i < TM; i++)
#pragma unroll
                for (int j = 0; j < TN; j++)
                    acc[i][j] = fmaf(ra[i], rb[j], acc[i][j]);
        }
        __syncthreads();
    }

#pragma unroll
    for (int i = 0; i < TM; i++) {
        const long long r = row0 + ty * TM + i;
#pragma unroll
        for (int j = 0; j < TN; j += 4) {
            const int c = col0 + tx * TN + j;
            float4 v;
            v.x = acc[i][j + 0] + bias[c + 0];
            v.y = acc[i][j + 1] + bias[c + 1];
            v.z = acc[i][j + 2] + bias[c + 2];
            v.w = acc[i][j + 3] + bias[c + 3];
            if (res) {
                const float4 rv = *reinterpret_cast<const float4*>(&res[r * N + c]);
                v.x += rv.x; v.y += rv.y; v.z += rv.z; v.w += rv.w;
            }
            *reinterpret_cast<float4*>(&C[r * N + c]) = v;
        }
    }
}

// ---------------- tiled SGEMM TN with gelu epilogue: C = gelu(A^T @ B) ----------------
// A is (K x M) row-major (lda = M). Batched via blockIdx.z.
__global__ __launch_bounds__(256) void gemm_tn_gelu(const float* __restrict__ A,
                                                    const float* __restrict__ B,
                                                    float* __restrict__ C,
                                                    int M, int N, int K,
                                                    long long sA, long long sB, long long sC)
{
    __shared__ float As[BKT][BM];
    __shared__ float Bs[BKT][BN];

    const int bz = blockIdx.z;
    A += bz * sA;
    B += bz * sB;
    C += bz * sC;

    const int tid  = threadIdx.x;
    const int row0 = blockIdx.y * BM;
    const int col0 = blockIdx.x * BN;

    const int l_row = tid >> 5;            // 0..7 (k within tile)
    const int l_col = (tid & 31) * 4;      // 0..124

    const int tx = tid & 15, ty = tid >> 4;

    float acc[TM][TN] = {};
    float ra[TM], rb[TN];

    for (int k0 = 0; k0 < K; k0 += BKT) {
        *reinterpret_cast<float4*>(&As[l_row][l_col]) =
            *reinterpret_cast<const float4*>(&A[(long long)(k0 + l_row) * M + row0 + l_col]);
        *reinterpret_cast<float4*>(&Bs[l_row][l_col]) =
            *reinterpret_cast<const float4*>(&B[(long long)(k0 + l_row) * N + col0 + l_col]);
        __syncthreads();
#pragma unroll
        for (int kk = 0; kk < BKT; kk++) {
#pragma unroll
            for (int i = 0; i < TM; i++) ra[i] = As[kk][ty * TM + i];
#pragma unroll
            for (int j = 0; j < TN; j++) rb[j] = Bs[kk][tx * TN + j];
#pragma unroll
            for (int i = 0; i < TM; i++)
#pragma unroll
                for (int j = 0; j < TN; j++)
                    acc[i][j] = fmaf(ra[i], rb[j], acc[i][j]);
        }
        __syncthreads();
    }

#pragma unroll
    for (int i = 0; i < TM; i++) {
        const long long r = row0 + ty * TM + i;
#pragma unroll
        for (int j = 0; j < TN; j += 4) {
            const int c = col0 + tx * TN + j;
            float4 v;
            v.x = acc[i][j + 0]; v.y = acc[i][j + 1];
            v.z = acc[i][j + 2]; v.w = acc[i][j + 3];
            v.x = 0.5f * v.x * (1.0f + erff(v.x * 0.70710678118654752f));
            v.y = 0.5f * v.y * (1.0f + erff(v.y * 0.70710678118654752f));
            v.z = 0.5f * v.z * (1.0f + erff(v.z * 0.70710678118654752f));
            v.w = 0.5f * v.w * (1.0f + erff(v.w * 0.70710678118654752f));
            *reinterpret_cast<float4*>(&C[r * N + c]) = v;
        }
    }
}

// ---------------- GLU (+ optional per-batch style scale) ----------------
__global__ void glu_scale(const float* __restrict__ h, const float* __restrict__ s,
                          float* __restrict__ o, int H, long long total)
{
    const long long idx = (long long)blockIdx.x * blockDim.x + threadIdx.x;
    if (idx >= total) return;
    const long long i = idx / H;
    const int j = (int)(idx - i * H);
    const float a  = h[i * 2 * H + j];
    const float gt = h[i * 2 * H + H + j];
    float v = a / (1.0f + expf(-gt));
    if (s) v *= s[(i / Tt) * H + j];
    o[idx] = v;
}

// ---------------- tiny style-vector GEMM ----------------
__global__ void small_gemm(const float* __restrict__ w, int ldw_batch,
                           const float* __restrict__ W, const float* __restrict__ bias,
                           float* __restrict__ out, int K, int N, int total)
{
    const int idx = blockIdx.x * blockDim.x + threadIdx.x;
    if (idx >= total) return;
    const int b = idx / N, n = idx - b * N;
    const float* wr = w + (long long)b * ldw_batch;
    float acc = bias[n];
    for (int k = 0; k < K; k++) acc = fmaf(wr[k], W[(long long)k * N + n], acc);
    out[idx] = acc;
}

// ---------------- launch ----------------
static inline void* symaddr(const void* s) { void* p = nullptr; cudaGetSymbolAddress(&p, s); return p; }

extern "C" void kernel_launch(void* const* d_in, const int* in_sizes, int n_in,
                              void* d_out, int out_size)
{
    const float* x     = (const float*)d_in[0];
    const float* w     = (const float*)d_in[1];
    const float* ln1_g = (const float*)d_in[2];
    const float* ln1_b = (const float*)d_in[3];
    const float* ln2_g = (const float*)d_in[4];
    const float* ln2_b = (const float*)d_in[5];
    const float* g1_W  = (const float*)d_in[6];
    const float* g1_b  = (const float*)d_in[7];
    const float* s1_W  = (const float*)d_in[8];
    const float* s1_b  = (const float*)d_in[9];
    const float* m1_W  = (const float*)d_in[10];
    const float* m1_b  = (const float*)d_in[11];
    const float* g2_W  = (const float*)d_in[12];
    const float* g2_b  = (const float*)d_in[13];
    const float* s2_W  = (const float*)d_in[14];
    const float* s2_b  = (const float*)d_in[15];
    const float* m2_W  = (const float*)d_in[16];
    const float* m2_b  = (const float*)d_in[17];
    const float* gs_W  = (const float*)d_in[18];
    const float* gs_b  = (const float*)d_in[19];
    const float* ss_W  = (const float*)d_in[20];
    const float* ss_b  = (const float*)d_in[21];
    const float* ms_W  = (const float*)d_in[22];
    const float* ms_b  = (const float*)d_in[23];
    const float* r1_W  = (const float*)d_in[24];
    const float* r1_b  = (const float*)d_in[25];
    const float* r2_W  = (const float*)d_in[26];
    const float* r2_b  = (const float*)d_in[27];
    float* out = (float*)d_out;

    float* xln = (float*)symaddr(g_xln);
    float* x2  = (float*)symaddr(g_x2);
    float* h   = (float*)symaddr(g_h);
    float* a   = (float*)symaddr(g_a);
    float* h1  = (float*)symaddr(g_h1);
    float* h2  = (float*)symaddr(g_h2);
    float* mix = (float*)symaddr(g_mix);
    float* s1  = (float*)symaddr(g_s1);
    float* s2  = (float*)symaddr(g_s2);
    float* ssv = (float*)symaddr(g_ss);
    float* zb  = (float*)symaddr(g_zero);

    // 1) xln = LN(x; ln1)
    ln_kernel<<<MTOK, 256>>>(x, ln1_g, ln1_b, xln);

    // 2) style vectors
    small_gemm<<<(Bb * (H1h/2) + 255) / 256, 256>>>(w,       2 * WDd, s1_W, s1_b, s1,  WDd, H1h/2, Bb * (H1h/2));
    small_gemm<<<(Bb * (H1h/2) + 255) / 256, 256>>>(w,       2 * WDd, s2_W, s2_b, s2,  WDd, H1h/2, Bb * (H1h/2));
    small_gemm<<<(Bb * (CDd/2) + 255) / 256, 256>>>(w + WDd, 2 * WDd, ss_W, ss_b, ssv, WDd, CDd/2, Bb * (CDd/2));

    // 3-5) h1 branch
    gemm_nn<<<dim3(H1h / BN, MTOK / BM, 1), 256>>>(xln, g1_W, h, g1_b, nullptr, MTOK, H1h, Cc, 0, 0, 0);
    glu_scale<<<(int)(((long long)MTOK * (H1h/2) + 255) / 256), 256>>>(h, s1, a, H1h/2, (long long)MTOK * (H1h/2));
    gemm_nn<<<dim3(TDd / BN, MTOK / BM, 1), 256>>>(a, m1_W, h1, m1_b, nullptr, MTOK, TDd, H1h/2, 0, 0, 0);

    // 6-8) h2 branch
    gemm_nn<<<dim3(H1h / BN, MTOK / BM, 1), 256>>>(xln, g2_W, h, g2_b, nullptr, MTOK, H1h, Cc, 0, 0, 0);
    glu_scale<<<(int)(((long long)MTOK * (H1h/2) + 255) / 256), 256>>>(h, s2, a, H1h/2, (long long)MTOK * (H1h/2));
    gemm_nn<<<dim3(TDd / BN, MTOK / BM, 1), 256>>>(a, m2_W, h2, m2_b, nullptr, MTOK, TDd, H1h/2, 0, 0, 0);

    // 9) mix[b] = gelu(h1[b]^T @ xln[b])   (M=TD, N=C, K=T), batched over B
    gemm_tn_gelu<<<dim3(Cc / BN, TDd / BM, Bb), 256>>>(h1, xln, mix, TDd, Cc, Tt,
                                                       (long long)Tt * TDd, (long long)Tt * Cc,
                                                       (long long)TDd * Cc);

    // 10) x2[b] = xln[b] + h2[b] @ mix[b]   (M=T, N=C, K=TD), batched, zero bias, residual=xln
    gemm_nn<<<dim3(Cc / BN, Tt / BM, Bb), 256>>>(h2, mix, x2, zb, xln, Tt, Cc, TDd,
                                                 (long long)Tt * TDd, (long long)TDd * Cc,
                                                 (long long)Tt * Cc);

    // 11) xln2 = LN(x2; ln2) -> reuse xln buffer
    ln_kernel<<<MTOK, 256>>>(x2, ln2_g, ln2_b, xln);

    // 12) Hs = xln2 @ gs_W + gs_b   (16384 x 3072)
    gemm_nn<<<dim3(CDd / BN, MTOK / BM, 1), 256>>>(xln, gs_W, h, gs_b, nullptr, MTOK, CDd, Cc, 0, 0, 0);

    // 13) a = glu(Hs) * ss
    glu_scale<<<(int)(((long long)MTOK * (CDd/2) + 255) / 256), 256>>>(h, ssv, a, CDd/2, (long long)MTOK * (CDd/2));

    // 14) x3 = x2 + a @ ms_W + ms_b  (in-place residual on x2)
    gemm_nn<<<dim3(Cc / BN, MTOK / BM, 1), 256>>>(a, ms_W, x2, ms_b, x2, MTOK, Cc, CDd/2, 0, 0, 0);

    // 15) Hr = x3 @ r1_W + r1_b
    gemm_nn<<<dim3(Cc / BN, MTOK / BM, 1), 256>>>(x2, r1_W, h, r1_b, nullptr, MTOK, Cc, Cc, 0, 0, 0);

    // 16) a = glu(Hr)
    glu_scale<<<(int)(((long long)MTOK * (Cc/2) + 255) / 256), 256>>>(h, nullptr, a, Cc/2, (long long)MTOK * (Cc/2));

    // 17) out = a @ r2_W + r2_b
    gemm_nn<<<dim3(Cc / BN, MTOK / BM, 1), 256>>>(a, r2_W, out, r2_b, nullptr, MTOK, Cc, Cc/2, 0, 0, 0);
}

// round 5
// speedup vs baseline: 2.4495x; 2.4495x over previous
#include <cuda_runtime.h>
#include <cuda_bf16.h>
#include <cstdint>
#include <math.h>

// ---------------- problem constants ----------------
#define Bb   8
#define Tt   2048
#define Cc   768
#define WDd  512
#define TDd  384
#define CDd  3072
#define H1h  768
#define MTOK (Bb * Tt)          // 16384

// ---------------- scratch (device globals; no allocation) ----------------
__device__ float g_xln [MTOK * Cc];
__device__ float g_x2  [MTOK * Cc];
__device__ float g_h   [MTOK * CDd];
__device__ float g_a   [MTOK * (CDd/2)];
__device__ float g_h1  [MTOK * TDd];
__device__ float g_h2  [MTOK * TDd];
__device__ float g_mix [Bb * TDd * Cc];
__device__ float g_h1t [Bb * TDd * Tt];
__device__ float g_xlnT[Bb * Cc * Tt];
__device__ float g_mixT[Bb * Cc * TDd];
__device__ float g_wT  [CDd * Cc];        // largest transposed weight: 3072x768
__device__ float g_s1  [Bb * (H1h/2)];
__device__ float g_s2  [Bb * (H1h/2)];
__device__ float g_ss  [Bb * (CDd/2)];
__device__ float g_zero[CDd];             // zero bias

// ---------------- helpers ----------------
// pack two floats' bf16(hi) parts into one u32 (low = x)
__device__ __forceinline__ uint32_t pack_hi(float x, float y) {
    __nv_bfloat162 v;
    v.x = __float2bfloat16_rn(x);
    v.y = __float2bfloat16_rn(y);
    return *reinterpret_cast<uint32_t*>(&v);
}
// pack two floats' residual parts: lo = bf16(x - float(bf16(x)))
__device__ __forceinline__ uint32_t pack_lo(float x, float y) {
    __nv_bfloat162 v;
    float hx = __bfloat162float(__float2bfloat16_rn(x));
    float hy = __bfloat162float(__float2bfloat16_rn(y));
    v.x = __float2bfloat16_rn(x - hx);
    v.y = __float2bfloat16_rn(y - hy);
    return *reinterpret_cast<uint32_t*>(&v);
}

__device__ __forceinline__ void mma_bf16(float* c, const uint32_t* a,
                                         uint32_t b0, uint32_t b1) {
    asm volatile(
        "mma.sync.aligned.m16n8k16.row.col.f32.bf16.bf16.f32 "
        "{%0,%1,%2,%3}, {%4,%5,%6,%7}, {%8,%9}, {%0,%1,%2,%3};"
        : "+f"(c[0]), "+f"(c[1]), "+f"(c[2]), "+f"(c[3])
        : "r"(a[0]), "r"(a[1]), "r"(a[2]), "r"(a[3]), "r"(b0), "r"(b1));
}

// ================= split-bf16 (bf16x3) mma GEMM =================
// C[M,N] = A[M,K](rm) @ Bt[N,K]^T (+bias[N]) (+res) ; ACT: 0=none, 1=exact gelu
// CTA tile 128x128, BK=32. SMEM row stride 80B (32 bf16 + 8 pad) -> conflict-free
// fragment LDS. 8 tiles: {A,B}x{hi,lo}x{2 buffers} = 81920 B.
#define LDB 80                       // bytes per smem row
#define TILE_B (128 * LDB)           // 10240 bytes per tile
#define GSMEM_SZ (8 * TILE_B)        // 81920

template <int ACT>
__global__ void __launch_bounds__(256, 1) gemm_bf3(
    const float* __restrict__ A, const float* __restrict__ Bt, float* __restrict__ C,
    const float* __restrict__ bias, const float* __restrict__ res,
    int M, int N, int K,
    long long sA, long long sB, long long sC, long long sR)
{
    extern __shared__ char smem[];

    const int tid = threadIdx.x, wid = tid >> 5, lane = tid & 31;
    const int g = lane >> 2, tg = lane & 3;
    const int wm = (wid >> 1) * 32;        // 4 warps along m
    const int wn = (wid & 1) * 64;         // 2 warps along n

    const int bz = blockIdx.z;
    A  += bz * sA;
    Bt += bz * sB;
    C  += bz * sC;
    if (res) res += bz * sR;

    const int row0 = blockIdx.y * 128;
    const int col0 = blockIdx.x * 128;

    const int nIter = K >> 5;

    float4 sa[4], sbv[4];

    // stage G->R for iter 0
    {
        const float* Ag = A + (long long)row0 * K;
        const float* Bg = Bt + (long long)col0 * K;
#pragma unroll
        for (int t = 0; t < 4; t++) {
            const int idx = tid + t * 256;
            const int r = idx >> 3, c4 = (idx & 7) << 2;
            sa[t]  = *(const float4*)(Ag + (long long)r * K + c4);
            sbv[t] = *(const float4*)(Bg + (long long)r * K + c4);
        }
    }
    // R->S buffer 0
    {
        char* Ah = smem;                    // A_hi
        char* Al = smem + TILE_B;           // A_lo
        char* Bh = smem + 2 * TILE_B;       // B_hi
        char* Bl = smem + 3 * TILE_B;       // B_lo
#pragma unroll
        for (int t = 0; t < 4; t++) {
            const int idx = tid + t * 256;
            const int r = idx >> 3, c4 = (idx & 7) << 2;
            const uint32_t off = r * LDB + c4 * 2;
            *(uint32_t*)(Ah + off)     = pack_hi(sa[t].x, sa[t].y);
            *(uint32_t*)(Ah + off + 4) = pack_hi(sa[t].z, sa[t].w);
            *(uint32_t*)(Al + off)     = pack_lo(sa[t].x, sa[t].y);
            *(uint32_t*)(Al + off + 4) = pack_lo(sa[t].z, sa[t].w);
            *(uint32_t*)(Bh + off)     = pack_hi(sbv[t].x, sbv[t].y);
            *(uint32_t*)(Bh + off + 4) = pack_hi(sbv[t].z, sbv[t].w);
            *(uint32_t*)(Bl + off)     = pack_lo(sbv[t].x, sbv[t].y);
            *(uint32_t*)(Bl + off + 4) = pack_lo(sbv[t].z, sbv[t].w);
        }
    }
    __syncthreads();

    float acc[2][8][4];
#pragma unroll
    for (int mt = 0; mt < 2; mt++)
#pragma unroll
        for (int nt = 0; nt < 8; nt++)
#pragma unroll
            for (int q = 0; q < 4; q++) acc[mt][nt][q] = 0.f;

    for (int i = 0; i < nIter; i++) {
        const int p = i & 1;
        char* Ah = smem + p * 4 * TILE_B;
        char* Al = Ah + TILE_B;
        char* Bh = Ah + 2 * TILE_B;
        char* Bl = Ah + 3 * TILE_B;

        // stage next G->R
        if (i + 1 < nIter) {
            const float* Ag = A + (long long)row0 * K + (i + 1) * 32;
            const float* Bg = Bt + (long long)col0 * K + (i + 1) * 32;
#pragma unroll
            for (int t = 0; t < 4; t++) {
                const int idx = tid + t * 256;
                const int r = idx >> 3, c4 = (idx & 7) << 2;
                sa[t]  = *(const float4*)(Ag + (long long)r * K + c4);
                sbv[t] = *(const float4*)(Bg + (long long)r * K + c4);
            }
        }

        // compute on buffer p: 2 k16 steps
#pragma unroll
        for (int kk = 0; kk < 2; kk++) {
            const int kb = kk * 32 + tg * 4;   // byte offset of this thread's k pair
            uint32_t ah[2][4], al[2][4];
#pragma unroll
            for (int mt = 0; mt < 2; mt++) {
                const int rm = wm + mt * 16;
                const uint32_t o0 = (rm + g) * LDB + kb;
                const uint32_t o1 = (rm + 8 + g) * LDB + kb;
                ah[mt][0] = *(const uint32_t*)(Ah + o0);
                ah[mt][1] = *(const uint32_t*)(Ah + o1);
                ah[mt][2] = *(const uint32_t*)(Ah + o0 + 16);
                ah[mt][3] = *(const uint32_t*)(Ah + o1 + 16);
                al[mt][0] = *(const uint32_t*)(Al + o0);
                al[mt][1] = *(const uint32_t*)(Al + o1);
                al[mt][2] = *(const uint32_t*)(Al + o0 + 16);
                al[mt][3] = *(const uint32_t*)(Al + o1 + 16);
            }
#pragma unroll
            for (int nt = 0; nt < 8; nt++) {
                const int cn = wn + nt * 8 + g;
                const uint32_t ob = cn * LDB + kb;
                const uint32_t bh0 = *(const uint32_t*)(Bh + ob);
                const uint32_t bh1 = *(const uint32_t*)(Bh + ob + 16);
                const uint32_t bl0 = *(const uint32_t*)(Bl + ob);
                const uint32_t bl1 = *(const uint32_t*)(Bl + ob + 16);
                mma_bf16(acc[0][nt], ah[0], bh0, bh1);
                mma_bf16(acc[1][nt], ah[1], bh0, bh1);
                mma_bf16(acc[0][nt], ah[0], bl0, bl1);
                mma_bf16(acc[1][nt], ah[1], bl0, bl1);
                mma_bf16(acc[0][nt], al[0], bh0, bh1);
                mma_bf16(acc[1][nt], al[1], bh0, bh1);
            }
        }

        if (i + 1 < nIter) {
            __syncthreads();
            char* Ahn = smem + (p ^ 1) * 4 * TILE_B;
            char* Aln = Ahn + TILE_B;
            char* Bhn = Ahn + 2 * TILE_B;
            char* Bln = Ahn + 3 * TILE_B;
#pragma unroll
            for (int t = 0; t < 4; t++) {
                const int idx = tid + t * 256;
                const int r = idx >> 3, c4 = (idx & 7) << 2;
                const uint32_t off = r * LDB + c4 * 2;
                *(uint32_t*)(Ahn + off)     = pack_hi(sa[t].x, sa[t].y);
                *(uint32_t*)(Ahn + off + 4) = pack_hi(sa[t].z, sa[t].w);
                *(uint32_t*)(Aln + off)     = pack_lo(sa[t].x, sa[t].y);
                *(uint32_t*)(Aln + off + 4) = pack_lo(sa[t].z, sa[t].w);
                *(uint32_t*)(Bhn + off)     = pack_hi(sbv[t].x, sbv[t].y);
                *(uint32_t*)(Bhn + off + 4) = pack_hi(sbv[t].z, sbv[t].w);
                *(uint32_t*)(Bln + off)     = pack_lo(sbv[t].x, sbv[t].y);
                *(uint32_t*)(Bln + off + 4) = pack_lo(sbv[t].z, sbv[t].w);
            }
            __syncthreads();
        }
    }

    // ---- epilogue ----
#pragma unroll
    for (int mt = 0; mt < 2; mt++) {
        const int r = row0 + wm + mt * 16 + g;
#pragma unroll
        for (int nt = 0; nt < 8; nt++) {
            const int c = col0 + wn + nt * 8 + tg * 2;
            const float bx = __ldg(&bias[c]), by = __ldg(&bias[c + 1]);
            float v0 = acc[mt][nt][0] + bx;
            float v1 = acc[mt][nt][1] + by;
            float v2 = acc[mt][nt][2] + bx;
            float v3 = acc[mt][nt][3] + by;
            if (res) {
                const float2 r0 = *(const float2*)(res + (long long)r * N + c);
                const float2 r1 = *(const float2*)(res + (long long)(r + 8) * N + c);
                v0 += r0.x; v1 += r0.y; v2 += r1.x; v3 += r1.y;
            }
            if (ACT == 1) {
                v0 = 0.5f * v0 * (1.0f + erff(v0 * 0.70710678118654752f));
                v1 = 0.5f * v1 * (1.0f + erff(v1 * 0.70710678118654752f));
                v2 = 0.5f * v2 * (1.0f + erff(v2 * 0.70710678118654752f));
                v3 = 0.5f * v3 * (1.0f + erff(v3 * 0.70710678118654752f));
            }
            *(float2*)(C + (long long)r * N + c)       = make_float2(v0, v1);
            *(float2*)(C + (long long)(r + 8) * N + c) = make_float2(v2, v3);
        }
    }
}

// ================= transpose: out[Cn][R] = in[R][Cn], batched =================
__global__ void transpose_k(const float* __restrict__ in, float* __restrict__ out,
                            int R, int Cn, long long sIn, long long sOut)
{
    __shared__ float t[32][33];
    const int bz = blockIdx.z;
    in  += bz * sIn;
    out += bz * sOut;
    const int c0 = blockIdx.x * 32, r0 = blockIdx.y * 32;
    const int x = threadIdx.x, y = threadIdx.y;   // 32 x 8
#pragma unroll
    for (int dy = 0; dy < 32; dy += 8)
        t[y + dy][x] = in[(long long)(r0 + y + dy) * Cn + c0 + x];
    __syncthreads();
#pragma unroll
    for (int dy = 0; dy < 32; dy += 8)
        out[(long long)(c0 + y + dy) * R + r0 + x] = t[x][y + dy];
}

// ================= LayerNorm (C=768), one block per row =================
__global__ __launch_bounds__(256) void ln_kernel(const float* __restrict__ x,
                                                 const float* __restrict__ g,
                                                 const float* __restrict__ b,
                                                 float* __restrict__ o)
{
    const int row = blockIdx.x;
    const float* xr = x + (long long)row * Cc;
    float* orow = o + (long long)row * Cc;
    const int tid = threadIdx.x;

    float v0 = xr[tid], v1 = xr[tid + 256], v2 = xr[tid + 512];
    float s = v0 + v1 + v2;
    float q = v0 * v0 + v1 * v1 + v2 * v2;
    for (int off = 16; off > 0; off >>= 1) {
        s += __shfl_down_sync(0xffffffff, s, off);
        q += __shfl_down_sync(0xffffffff, q, off);
    }
    __shared__ float ssm[8], sqm[8];
    const int wid = tid >> 5, lid = tid & 31;
    if (lid == 0) { ssm[wid] = s; sqm[wid] = q; }
    __syncthreads();
    if (tid < 8) { s = ssm[tid]; q = sqm[tid]; }
    if (wid == 0) {
        for (int off = 4; off > 0; off >>= 1) {
            s += __shfl_down_sync(0x000000ff, s, off);
            q += __shfl_down_sync(0x000000ff, q, off);
        }
        if (tid == 0) { ssm[0] = s; sqm[0] = q; }
    }
    __syncthreads();
    const float mu  = ssm[0] * (1.0f / Cc);
    const float var = sqm[0] * (1.0f / Cc) - mu * mu;
    const float rs  = rsqrtf(var + 1e-6f);
    orow[tid]       = (v0 - mu) * rs * g[tid]       + b[tid];
    orow[tid + 256] = (v1 - mu) * rs * g[tid + 256] + b[tid + 256];
    orow[tid + 512] = (v2 - mu) * rs * g[tid + 512] + b[tid + 512];
}

// ================= GLU (vectorized, optional per-batch style scale) =============
__global__ void glu4(const float* __restrict__ h, const float* __restrict__ s,
                     float* __restrict__ o, int H, long long rows)
{
    const long long tot = rows * (H >> 2);
    const long long idx = (long long)blockIdx.x * blockDim.x + threadIdx.x;
    if (idx >= tot) return;
    const long long i = idx / (H >> 2);
    const int j = (int)(idx - i * (H >> 2)) << 2;
    const float4 a = *(const float4*)&h[i * 2 * H + j];
    const float4 gt = *(const float4*)&h[i * 2 * H + H + j];
    float4 v;
    v.x = a.x / (1.0f + expf(-gt.x));
    v.y = a.y / (1.0f + expf(-gt.y));
    v.z = a.z / (1.0f + expf(-gt.z));
    v.w = a.w / (1.0f + expf(-gt.w));
    if (s) {
        const float4 sv = *(const float4*)&s[(i / Tt) * H + j];
        v.x *= sv.x; v.y *= sv.y; v.z *= sv.z; v.w *= sv.w;
    }
    *(float4*)&o[i * H + j] = v;
}

// ================= style vectors: out[b,n] = w[b,:]@W[:,n] + bias[n], K=512 ======
__global__ __launch_bounds__(256) void style_gemm(const float* __restrict__ w, int ldwb,
                                                  const float* __restrict__ W,
                                                  const float* __restrict__ bias,
                                                  float* __restrict__ out, int N)
{
    __shared__ float ws[WDd];
    __shared__ float red[8][32];
    const int b = blockIdx.y;
    const int n0 = blockIdx.x * 32;
    const float* wr = w + (long long)b * ldwb;
    for (int k = threadIdx.x; k < WDd; k += 256) ws[k] = wr[k];
    __syncthreads();
    const int lane = threadIdx.x & 31, sct = threadIdx.x >> 5;
    const int n = n0 + lane;
    float acc = 0.f;
#pragma unroll 4
    for (int k = sct * 64; k < sct * 64 + 64; k++)
        acc = fmaf(ws[k], W[(long long)k * N + n], acc);
    red[sct][lane] = acc;
    __syncthreads();
    if (sct == 0) {
        float a = red[0][lane];
#pragma unroll
        for (int j = 1; j < 8; j++) a += red[j][lane];
        out[(long long)b * N + n] = a + bias[n];
    }
}

// ================= launch =================
static inline void* symaddr(const void* s) { void* p = nullptr; cudaGetSymbolAddress(&p, s); return p; }

extern "C" void kernel_launch(void* const* d_in, const int* in_sizes, int n_in,
                              void* d_out, int out_size)
{
    const float* x     = (const float*)d_in[0];
    const float* w     = (const float*)d_in[1];
    const float* ln1_g = (const float*)d_in[2];
    const float* ln1_b = (const float*)d_in[3];
    const float* ln2_g = (const float*)d_in[4];
    const float* ln2_b = (const float*)d_in[5];
    const float* g1_W  = (const float*)d_in[6];
    const float* g1_b  = (const float*)d_in[7];
    const float* s1_W  = (const float*)d_in[8];
    const float* s1_b  = (const float*)d_in[9];
    const float* m1_W  = (const float*)d_in[10];
    const float* m1_b  = (const float*)d_in[11];
    const float* g2_W  = (const float*)d_in[12];
    const float* g2_b  = (const float*)d_in[13];
    const float* s2_W  = (const float*)d_in[14];
    const float* s2_b  = (const float*)d_in[15];
    const float* m2_W  = (const float*)d_in[16];
    const float* m2_b  = (const float*)d_in[17];
    const float* gs_W  = (const float*)d_in[18];
    const float* gs_b  = (const float*)d_in[19];
    const float* ss_W  = (const float*)d_in[20];
    const float* ss_b  = (const float*)d_in[21];
    const float* ms_W  = (const float*)d_in[22];
    const float* ms_b  = (const float*)d_in[23];
    const float* r1_W  = (const float*)d_in[24];
    const float* r1_b  = (const float*)d_in[25];
    const float* r2_W  = (const float*)d_in[26];
    const float* r2_b  = (const float*)d_in[27];
    float* out = (float*)d_out;

    float* xln  = (float*)symaddr(g_xln);
    float* x2   = (float*)symaddr(g_x2);
    float* h    = (float*)symaddr(g_h);
    float* a    = (float*)symaddr(g_a);
    float* h1   = (float*)symaddr(g_h1);
    float* h2   = (float*)symaddr(g_h2);
    float* mix  = (float*)symaddr(g_mix);
    float* h1t  = (float*)symaddr(g_h1t);
    float* xlnT = (float*)symaddr(g_xlnT);
    float* mixT = (float*)symaddr(g_mixT);
    float* wT   = (float*)symaddr(g_wT);
    float* s1   = (float*)symaddr(g_s1);
    float* s2   = (float*)symaddr(g_s2);
    float* ssv  = (float*)symaddr(g_ss);
    float* zb   = (float*)symaddr(g_zero);

    cudaFuncSetAttribute(gemm_bf3<0>, cudaFuncAttributeMaxDynamicSharedMemorySize, GSMEM_SZ);
    cudaFuncSetAttribute(gemm_bf3<1>, cudaFuncAttributeMaxDynamicSharedMemorySize, GSMEM_SZ);

    const dim3 tb(32, 8);

    // 1) xln = LN(x; ln1)
    ln_kernel<<<MTOK, 256>>>(x, ln1_g, ln1_b, xln);

    // 2) style vectors
    style_gemm<<<dim3((H1h/2)/32, Bb), 256>>>(w,       2*WDd, s1_W, s1_b, s1,  H1h/2);
    style_gemm<<<dim3((H1h/2)/32, Bb), 256>>>(w,       2*WDd, s2_W, s2_b, s2,  H1h/2);
    style_gemm<<<dim3((CDd/2)/32, Bb), 256>>>(w + WDd, 2*WDd, ss_W, ss_b, ssv, CDd/2);

    // 3) branch 1: h = xln @ g1_W + g1_b ; a = glu(h)*s1 ; h1 = a @ m1_W + m1_b
    transpose_k<<<dim3(H1h/32, Cc/32, 1), tb>>>(g1_W, wT, Cc, H1h, 0, 0);
    gemm_bf3<0><<<dim3(H1h/128, MTOK/128, 1), 256, GSMEM_SZ>>>(xln, wT, h, g1_b, nullptr,
        MTOK, H1h, Cc, 0, 0, 0, 0);
    glu4<<<(int)(((long long)MTOK*(H1h/2)/4 + 255)/256), 256>>>(h, s1, a, H1h/2, MTOK);
    transpose_k<<<dim3(TDd/32, TDd/32, 1), tb>>>(m1_W, wT, TDd, TDd, 0, 0);
    gemm_bf3<0><<<dim3(TDd/128, MTOK/128, 1), 256, GSMEM_SZ>>>(a, wT, h1, m1_b, nullptr,
        MTOK, TDd, H1h/2, 0, 0, 0, 0);

    // 4) branch 2
    transpose_k<<<dim3(H1h/32, Cc/32, 1), tb>>>(g2_W, wT, Cc, H1h, 0, 0);
    gemm_bf3<0><<<dim3(H1h/128, MTOK/128, 1), 256, GSMEM_SZ>>>(xln, wT, h, g2_b, nullptr,
        MTOK, H1h, Cc, 0, 0, 0, 0);
    glu4<<<(int)(((long long)MTOK*(H1h/2)/4 + 255)/256), 256>>>(h, s2, a, H1h/2, MTOK);
    transpose_k<<<dim3(TDd/32, TDd/32, 1), tb>>>(m2_W, wT, TDd, TDd, 0, 0);
    gemm_bf3<0><<<dim3(TDd/128, MTOK/128, 1), 256, GSMEM_SZ>>>(a, wT, h2, m2_b, nullptr,
        MTOK, TDd, H1h/2, 0, 0, 0, 0);

    // 5) mix[b] = gelu(h1[b]^T @ xln[b])
    transpose_k<<<dim3(TDd/32, Tt/32, Bb), tb>>>(h1, h1t, Tt, TDd,
        (long long)Tt*TDd, (long long)Tt*TDd);
    transpose_k<<<dim3(Cc/32, Tt/32, Bb), tb>>>(xln, xlnT, Tt, Cc,
        (long long)Tt*Cc, (long long)Tt*Cc);
    gemm_bf3<1><<<dim3(Cc/128, TDd/128, Bb), 256, GSMEM_SZ>>>(h1t, xlnT, mix, zb, nullptr,
        TDd, Cc, Tt, (long long)TDd*Tt, (long long)Cc*Tt, (long long)TDd*Cc, 0);

    // 6) x2[b] = xln[b] + h2[b] @ mix[b]
    transpose_k<<<dim3(Cc/32, TDd/32, Bb), tb>>>(mix, mixT, TDd, Cc,
        (long long)TDd*Cc, (long long)TDd*Cc);
    gemm_bf3<0><<<dim3(Cc/128, Tt/128, Bb), 256, GSMEM_SZ>>>(h2, mixT, x2, zb, xln,
        Tt, Cc, TDd, (long long)Tt*TDd, (long long)Cc*TDd, (long long)Tt*Cc, (long long)Tt*Cc);

    // 7) xln2 = LN(x2; ln2) (reuse xln buffer)
    ln_kernel<<<MTOK, 256>>>(x2, ln2_g, ln2_b, xln);

    // 8) Hs = xln2 @ gs_W + gs_b ; a = glu(Hs)*ss ; x3 = x2 + a @ ms_W + ms_b
    transpose_k<<<dim3(CDd/32, Cc/32, 1), tb>>>(gs_W, wT, Cc, CDd, 0, 0);
    gemm_bf3<0><<<dim3(CDd/128, MTOK/128, 1), 256, GSMEM_SZ>>>(xln, wT, h, gs_b, nullptr,
        MTOK, CDd, Cc, 0, 0, 0, 0);
    glu4<<<(int)(((long long)MTOK*(CDd/2)/4 + 255)/256), 256>>>(h, ssv, a, CDd/2, MTOK);
    transpose_k<<<dim3(Cc/32, (CDd/2)/32, 1), tb>>>(ms_W, wT, CDd/2, Cc, 0, 0);
    gemm_bf3<0><<<dim3(Cc/128, MTOK/128, 1), 256, GSMEM_SZ>>>(a, wT, x2, ms_b, x2,
        MTOK, Cc, CDd/2, 0, 0, 0, 0);

    // 9) head: Hr = x3 @ r1_W + r1_b ; a = glu(Hr) ; out = a @ r2_W + r2_b
    transpose_k<<<dim3(Cc/32, Cc/32, 1), tb>>>(r1_W, wT, Cc, Cc, 0, 0);
    gemm_bf3<0><<<dim3(Cc/128, MTOK/128, 1), 256, GSMEM_SZ>>>(x2, wT, h, r1_b, nullptr,
        MTOK, Cc, Cc, 0, 0, 0, 0);
    glu4<<<(int)(((long long)MTOK*(Cc/2)/4 + 255)/256), 256>>>(h, nullptr, a, Cc/2, MTOK);
    transpose_k<<<dim3(Cc/32, (Cc/2)/32, 1), tb>>>(r2_W, wT, Cc/2, Cc, 0, 0);
    gemm_bf3<0><<<dim3(Cc/128, MTOK/128, 1), 256, GSMEM_SZ>>>(a, wT, out, r2_b, nullptr,
        MTOK, Cc, Cc/2, 0, 0, 0, 0);
}

// round 7
// speedup vs baseline: 2.7048x; 1.1042x over previous
#include <cuda_runtime.h>
#include <cuda_bf16.h>
#include <cstdint>
#include <math.h>

// ---------------- problem constants ----------------
#define Bb   8
#define Tt   2048
#define Cc   768
#define WDd  512
#define TDd  384
#define CDd  3072
#define H1h  768
#define MTOK (Bb * Tt)          // 16384

// ---------------- fp32 scratch ----------------
__device__ float g_xf [MTOK * Cc];        // xln fp32 (residual + transpose src)
__device__ float g_x2 [MTOK * Cc];        // x2 / x3 fp32
__device__ float g_h  [MTOK * CDd];       // GEMM fp32 out (max 16384x3072)
__device__ float g_h1 [MTOK * TDd];
__device__ float g_mix[Bb * TDd * Cc];
__device__ float g_s1 [Bb * (H1h/2)];
__device__ float g_s2 [Bb * (H1h/2)];
__device__ float g_ss [Bb * (CDd/2)];
__device__ float g_zero[CDd];
__device__ float g_b12[2 * H1h];          // concat(g1_b, g2_b)

// ---------------- bf16 split operand buffers ----------------
__device__ __nv_bfloat16 g_xh [MTOK*Cc],        g_xl [MTOK*Cc];        // xln / xln2 split
__device__ __nv_bfloat16 g_a1h[MTOK*TDd],       g_a1l[MTOK*TDd];       // a1 / ar
__device__ __nv_bfloat16 g_a2h[MTOK*TDd],       g_a2l[MTOK*TDd];
__device__ __nv_bfloat16 g_ash[MTOK*(CDd/2)],   g_asl[MTOK*(CDd/2)];   // big glu out
__device__ __nv_bfloat16 g_h2h[MTOK*TDd],       g_h2l[MTOK*TDd];
__device__ __nv_bfloat16 g_h1th[Bb*TDd*Tt],     g_h1tl[Bb*TDd*Tt];
__device__ __nv_bfloat16 g_xTh[Bb*Cc*Tt],       g_xTl[Bb*Cc*Tt];
__device__ __nv_bfloat16 g_mTh[Bb*Cc*TDd],      g_mTl[Bb*Cc*TDd];
__device__ __nv_bfloat16 g_wTh[CDd*Cc],         g_wTl[CDd*Cc];         // transposed weight (max 3072x768)
__device__ __nv_bfloat16 g_x3h[MTOK*Cc],        g_x3l[MTOK*Cc];

// ---------------- helpers ----------------
__device__ __forceinline__ uint32_t smem_u32(const void* p) {
    uint32_t a;
    asm("{ .reg .u64 t; cvta.to.shared.u64 t, %1; cvt.u32.u64 %0, t; }" : "=r"(a) : "l"(p));
    return a;
}
__device__ __forceinline__ void cpa16(uint32_t s, const void* g) {
    asm volatile("cp.async.cg.shared.global [%0], [%1], 16;" :: "r"(s), "l"(g));
}
__device__ __forceinline__ void mma_bf16(float* c, const uint32_t* a,
                                         uint32_t b0, uint32_t b1) {
    asm volatile(
        "mma.sync.aligned.m16n8k16.row.col.f32.bf16.bf16.f32 "
        "{%0,%1,%2,%3}, {%4,%5,%6,%7}, {%8,%9}, {%0,%1,%2,%3};"
        : "+f"(c[0]), "+f"(c[1]), "+f"(c[2]), "+f"(c[3])
        : "r"(a[0]), "r"(a[1]), "r"(a[2]), "r"(a[3]), "r"(b0), "r"(b1));
}
__device__ __forceinline__ void split_one(float v, __nv_bfloat16& h, __nv_bfloat16& l) {
    h = __float2bfloat16_rn(v);
    l = __float2bfloat16_rn(v - __bfloat162float(h));
}

// ================= split-bf16 GEMM with cp.async pipeline =================
// C = A(M,K) @ Bt(N,K)^T + bias (+res); A/B given as precomputed (hi,lo) bf16.
// CTA tile 128x128, BK=32 bf16 (64B rows + 16B pad = 80B stride; conflict-free).
// 2 stages x 4 tiles x 10240B = 81920B smem; 2 CTAs/SM.
#define LDBB 80
#define TILE_B (128 * LDBB)
#define GSMEM_SZ (8 * TILE_B)

template <int ACT>
__global__ void __launch_bounds__(256, 2) gemm_sp(
    const __nv_bfloat16* __restrict__ Ah_, const __nv_bfloat16* __restrict__ Al_,
    const __nv_bfloat16* __restrict__ Bh_, const __nv_bfloat16* __restrict__ Bl_,
    float* __restrict__ Cf, __nv_bfloat16* __restrict__ Ch, __nv_bfloat16* __restrict__ Cl,
    const float* __restrict__ bias, const float* __restrict__ res,
    int M, int N, int K,
    long long sA, long long sB, long long sC, long long sR)
{
    extern __shared__ char smem[];
    const uint32_t sbase = smem_u32(smem);
    const int tid = threadIdx.x, wid = tid >> 5, lane = tid & 31;
    const int g = lane >> 2, tg = lane & 3;
    const int wm = (wid >> 1) * 32;
    const int wn = (wid & 1) * 64;

    const int bz = blockIdx.z;
    const long long ldb = (long long)K * 2;     // bytes per operand row

    const int row0 = blockIdx.y * 128;
    const int col0 = blockIdx.x * 128;

    const char* Agh = (const char*)(Ah_ + bz * sA) + (long long)row0 * ldb;
    const char* Agl = (const char*)(Al_ + bz * sA) + (long long)row0 * ldb;
    const char* Bgh = (const char*)(Bh_ + bz * sB) + (long long)col0 * ldb;
    const char* Bgl = (const char*)(Bl_ + bz * sB) + (long long)col0 * ldb;
    if (Cf) Cf += bz * sC;
    if (Ch) { Ch += bz * sC; Cl += bz * sC; }
    if (res) res += bz * sR;

    const int nIter = K >> 5;                   // >= 12 for all shapes here
    const int rr = tid >> 2;                    // 0..63
    const int cb = (tid & 3) * 16;              // 0/16/32/48

    auto issue = [&](int i) {
        const uint32_t sb0 = sbase + (uint32_t)(i & 1) * 4 * TILE_B;
        const long long ko = (long long)i * 64;
#pragma unroll
        for (int t = 0; t < 2; t++) {
            const int r = rr + t * 64;
            const long long go = (long long)r * ldb + ko + cb;
            const uint32_t so = (uint32_t)r * LDBB + cb;
            cpa16(sb0 + so,              Agh + go);
            cpa16(sb0 + TILE_B + so,     Agl + go);
            cpa16(sb0 + 2 * TILE_B + so, Bgh + go);
            cpa16(sb0 + 3 * TILE_B + so, Bgl + go);
        }
    };

    issue(0); asm volatile("cp.async.commit_group;");
    issue(1); asm volatile("cp.async.commit_group;");

    float acc[2][8][4];
#pragma unroll
    for (int mt = 0; mt < 2; mt++)
#pragma unroll
        for (int nt = 0; nt < 8; nt++)
#pragma unroll
            for (int q = 0; q < 4; q++) acc[mt][nt][q] = 0.f;

    for (int i = 0; i < nIter; i++) {
        asm volatile("cp.async.wait_group 1;");
        __syncthreads();
        const char* base = smem + (i & 1) * 4 * TILE_B;
        const char* tAh = base;
        const char* tAl = base + TILE_B;
        const char* tBh = base + 2 * TILE_B;
        const char* tBl = base + 3 * TILE_B;
#pragma unroll
        for (int kk = 0; kk < 2; kk++) {
            const int kb = kk * 32 + tg * 4;
            uint32_t ah[2][4], al[2][4];
#pragma unroll
            for (int mt = 0; mt < 2; mt++) {
                const int rm = wm + mt * 16;
                const uint32_t o0 = (rm + g) * LDBB + kb;
                const uint32_t o1 = (rm + 8 + g) * LDBB + kb;
                ah[mt][0] = *(const uint32_t*)(tAh + o0);
                ah[mt][1] = *(const uint32_t*)(tAh + o1);
                ah[mt][2] = *(const uint32_t*)(tAh + o0 + 16);
                ah[mt][3] = *(const uint32_t*)(tAh + o1 + 16);
                al[mt][0] = *(const uint32_t*)(tAl + o0);
                al[mt][1] = *(const uint32_t*)(tAl + o1);
                al[mt][2] = *(const uint32_t*)(tAl + o0 + 16);
                al[mt][3] = *(const uint32_t*)(tAl + o1 + 16);
            }
#pragma unroll
            for (int nt = 0; nt < 8; nt++) {
                const uint32_t ob = (wn + nt * 8 + g) * LDBB + kb;
                const uint32_t bh0 = *(const uint32_t*)(tBh + ob);
                const uint32_t bh1 = *(const uint32_t*)(tBh + ob + 16);
                const uint32_t bl0 = *(const uint32_t*)(tBl + ob);
                const uint32_t bl1 = *(const uint32_t*)(tBl + ob + 16);
                mma_bf16(acc[0][nt], ah[0], bh0, bh1);
                mma_bf16(acc[1][nt], ah[1], bh0, bh1);
                mma_bf16(acc[0][nt], ah[0], bl0, bl1);
                mma_bf16(acc[1][nt], ah[1], bl0, bl1);
                mma_bf16(acc[0][nt], al[0], bh0, bh1);
                mma_bf16(acc[1][nt], al[1], bh0, bh1);
            }
        }
        __syncthreads();
        if (i + 2 < nIter) issue(i + 2);
        asm volatile("cp.async.commit_group;");
    }
    asm volatile("cp.async.wait_all;");

    // ---- epilogue ----
#pragma unroll
    for (int mt = 0; mt < 2; mt++) {
        const int r = row0 + wm + mt * 16 + g;
#pragma unroll
        for (int nt = 0; nt < 8; nt++) {
            const int c = col0 + wn + nt * 8 + tg * 2;
            const float bx = __ldg(&bias[c]), by = __ldg(&bias[c + 1]);
            float v0 = acc[mt][nt][0] + bx;
            float v1 = acc[mt][nt][1] + by;
            float v2 = acc[mt][nt][2] + bx;
            float v3 = acc[mt][nt][3] + by;
            if (res) {
                const float2 r0 = *(const float2*)(res + (long long)r * N + c);
                const float2 r1 = *(const float2*)(res + (long long)(r + 8) * N + c);
                v0 += r0.x; v1 += r0.y; v2 += r1.x; v3 += r1.y;
            }
            if (ACT == 1) {
                v0 = 0.5f * v0 * (1.0f + erff(v0 * 0.70710678118654752f));
                v1 = 0.5f * v1 * (1.0f + erff(v1 * 0.70710678118654752f));
                v2 = 0.5f * v2 * (1.0f + erff(v2 * 0.70710678118654752f));
                v3 = 0.5f * v3 * (1.0f + erff(v3 * 0.70710678118654752f));
            }
            if (Cf) {
                *(float2*)(Cf + (long long)r * N + c)       = make_float2(v0, v1);
                *(float2*)(Cf + (long long)(r + 8) * N + c) = make_float2(v2, v3);
            }
            if (Ch) {
                __nv_bfloat162 h01, l01, h23, l23;
                split_one(v0, h01.x, l01.x); split_one(v1, h01.y, l01.y);
                split_one(v2, h23.x, l23.x); split_one(v3, h23.y, l23.y);
                *(__nv_bfloat162*)(Ch + (long long)r * N + c)       = h01;
                *(__nv_bfloat162*)(Cl + (long long)r * N + c)       = l01;
                *(__nv_bfloat162*)(Ch + (long long)(r + 8) * N + c) = h23;
                *(__nv_bfloat162*)(Cl + (long long)(r + 8) * N + c) = l23;
            }
        }
    }
}

// ================= transpose + split: out[Cn][R] = split(in[R][Cn]) ============
__global__ void transpose_split(const float* __restrict__ in,
                                __nv_bfloat16* __restrict__ oh,
                                __nv_bfloat16* __restrict__ ol,
                                int R, int Cn, long long sIn, long long sOut)
{
    __shared__ float t[32][33];
    const int bz = blockIdx.z;
    in += bz * sIn; oh += bz * sOut; ol += bz * sOut;
    const int c0 = blockIdx.x * 32, r0 = blockIdx.y * 32;
    const int x = threadIdx.x, y = threadIdx.y;   // 32 x 8
#pragma unroll
    for (int dy = 0; dy < 32; dy += 8)
        t[y + dy][x] = in[(long long)(r0 + y + dy) * Cn + c0 + x];
    __syncthreads();
#pragma unroll
    for (int dy = 0; dy < 32; dy += 8) {
        const float v = t[x][y + dy];
        __nv_bfloat16 h, l;
        split_one(v, h, l);
        const long long o = (long long)(c0 + y + dy) * R + r0 + x;
        oh[o] = h; ol[o] = l;
    }
}

// ================= LayerNorm + split (C=768) =================
__global__ __launch_bounds__(256) void ln_split(const float* __restrict__ x,
                                                const float* __restrict__ g,
                                                const float* __restrict__ b,
                                                float* __restrict__ of,
                                                __nv_bfloat16* __restrict__ oh,
                                                __nv_bfloat16* __restrict__ ol)
{
    const int row = blockIdx.x;
    const float* xr = x + (long long)row * Cc;
    const int tid = threadIdx.x;

    float v0 = xr[tid], v1 = xr[tid + 256], v2 = xr[tid + 512];
    float s = v0 + v1 + v2;
    float q = v0 * v0 + v1 * v1 + v2 * v2;
    for (int off = 16; off > 0; off >>= 1) {
        s += __shfl_down_sync(0xffffffff, s, off);
        q += __shfl_down_sync(0xffffffff, q, off);
    }
    __shared__ float ssm[8], sqm[8];
    const int wid = tid >> 5, lid = tid & 31;
    if (lid == 0) { ssm[wid] = s; sqm[wid] = q; }
    __syncthreads();
    if (tid < 8) { s = ssm[tid]; q = sqm[tid]; }
    if (wid == 0) {
        for (int off = 4; off > 0; off >>= 1) {
            s += __shfl_down_sync(0x000000ff, s, off);
            q += __shfl_down_sync(0x000000ff, q, off);
        }
        if (tid == 0) { ssm[0] = s; sqm[0] = q; }
    }
    __syncthreads();
    const float mu  = ssm[0] * (1.0f / Cc);
    const float var = sqm[0] * (1.0f / Cc) - mu * mu;
    const float rs  = rsqrtf(var + 1e-6f);

#pragma unroll
    for (int t = 0; t < 3; t++) {
        const int j = tid + t * 256;
        const float vv = t == 0 ? v0 : (t == 1 ? v1 : v2);
        const float v = (vv - mu) * rs * g[j] + b[j];
        const long long o = (long long)row * Cc + j;
        if (of) of[o] = v;
        __nv_bfloat16 h, l;
        split_one(v, h, l);
        oh[o] = h; ol[o] = l;
    }
}

// ================= GLU + split (optional style scale, general row stride) =======
__global__ void glu_split(const float* __restrict__ h, int rowStride, int H,
                          const float* __restrict__ s,
                          __nv_bfloat16* __restrict__ oh,
                          __nv_bfloat16* __restrict__ ol)
{
    const long long tot = (long long)MTOK * (H >> 2);
    const long long idx = (long long)blockIdx.x * blockDim.x + threadIdx.x;
    if (idx >= tot) return;
    const long long i = idx / (H >> 2);
    const int j = (int)(idx - i * (H >> 2)) << 2;
    const float4 a  = *(const float4*)&h[i * rowStride + j];
    const float4 gt = *(const float4*)&h[i * rowStride + H + j];
    float4 v;
    v.x = a.x / (1.0f + expf(-gt.x));
    v.y = a.y / (1.0f + expf(-gt.y));
    v.z = a.z / (1.0f + expf(-gt.z));
    v.w = a.w / (1.0f + expf(-gt.w));
    if (s) {
        const float4 sv = *(const float4*)&s[(i / Tt) * H + j];
        v.x *= sv.x; v.y *= sv.y; v.z *= sv.z; v.w *= sv.w;
    }
    __nv_bfloat162 h0, l0, h1, l1;
    split_one(v.x, h0.x, l0.x); split_one(v.y, h0.y, l0.y);
    split_one(v.z, h1.x, l1.x); split_one(v.w, h1.y, l1.y);
    const long long o = i * H + j;
    *(__nv_bfloat162*)(oh + o)     = h0;
    *(__nv_bfloat162*)(ol + o)     = l0;
    *(__nv_bfloat162*)(oh + o + 2) = h1;
    *(__nv_bfloat162*)(ol + o + 2) = l1;
}

// ================= style vectors (fp32 tiny GEMM, K=512) =================
__global__ __launch_bounds__(256) void style_gemm(const float* __restrict__ w, int ldwb,
                                                  const float* __restrict__ W,
                                                  const float* __restrict__ bias,
                                                  float* __restrict__ out, int N)
{
    __shared__ float ws[WDd];
    __shared__ float red[8][32];
    const int b = blockIdx.y;
    const int n0 = blockIdx.x * 32;
    const float* wr = w + (long long)b * ldwb;
    for (int k = threadIdx.x; k < WDd; k += 256) ws[k] = wr[k];
    __syncthreads();
    const int lane = threadIdx.x & 31, sct = threadIdx.x >> 5;
    const int n = n0 + lane;
    float acc = 0.f;
#pragma unroll 4
    for (int k = sct * 64; k < sct * 64 + 64; k++)
        acc = fmaf(ws[k], W[(long long)k * N + n], acc);
    red[sct][lane] = acc;
    __syncthreads();
    if (sct == 0) {
        float a = red[0][lane];
#pragma unroll
        for (int j = 1; j < 8; j++) a += red[j][lane];
        out[(long long)b * N + n] = a + bias[n];
    }
}

// ================= concat two bias vectors =================
__global__ void concat2(const float* __restrict__ a, const float* __restrict__ b,
                        float* __restrict__ o, int n)
{
    const int i = blockIdx.x * blockDim.x + threadIdx.x;
    if (i < n) o[i] = a[i];
    else if (i < 2 * n) o[i] = b[i - n];
}

// ================= launch =================
static inline void* symaddr(const void* s) { void* p = nullptr; cudaGetSymbolAddress(&p, s); return p; }

extern "C" void kernel_launch(void* const* d_in, const int* in_sizes, int n_in,
                              void* d_out, int out_size)
{
    const float* x     = (const float*)d_in[0];
    const float* w     = (const float*)d_in[1];
    const float* ln1_g = (const float*)d_in[2];
    const float* ln1_b = (const float*)d_in[3];
    const float* ln2_g = (const float*)d_in[4];
    const float* ln2_b = (const float*)d_in[5];
    const float* g1_W  = (const float*)d_in[6];
    const float* g1_b  = (const float*)d_in[7];
    const float* s1_W  = (const float*)d_in[8];
    const float* s1_b  = (const float*)d_in[9];
    const float* m1_W  = (const float*)d_in[10];
    const float* m1_b  = (const float*)d_in[11];
    const float* g2_W  = (const float*)d_in[12];
    const float* g2_b  = (const float*)d_in[13];
    const float* s2_W  = (const float*)d_in[14];
    const float* s2_b  = (const float*)d_in[15];
    const float* m2_W  = (const float*)d_in[16];
    const float* m2_b  = (const float*)d_in[17];
    const float* gs_W  = (const float*)d_in[18];
    const float* gs_b  = (const float*)d_in[19];
    const float* ss_W  = (const float*)d_in[20];
    const float* ss_b  = (const float*)d_in[21];
    const float* ms_W  = (const float*)d_in[22];
    const float* ms_b  = (const float*)d_in[23];
    const float* r1_W  = (const float*)d_in[24];
    const float* r1_b  = (const float*)d_in[25];
    const float* r2_W  = (const float*)d_in[26];
    const float* r2_b  = (const float*)d_in[27];
    float* out = (float*)d_out;

    float* xf   = (float*)symaddr(g_xf);
    float* x2   = (float*)symaddr(g_x2);
    float* h    = (float*)symaddr(g_h);
    float* h1   = (float*)symaddr(g_h1);
    float* mix  = (float*)symaddr(g_mix);
    float* s1   = (float*)symaddr(g_s1);
    float* s2   = (float*)symaddr(g_s2);
    float* ssv  = (float*)symaddr(g_ss);
    float* zb   = (float*)symaddr(g_zero);
    float* b12  = (float*)symaddr(g_b12);
    __nv_bfloat16* xh  = (__nv_bfloat16*)symaddr(g_xh);
    __nv_bfloat16* xl  = (__nv_bfloat16*)symaddr(g_xl);
    __nv_bfloat16* a1h = (__nv_bfloat16*)symaddr(g_a1h);
    __nv_bfloat16* a1l = (__nv_bfloat16*)symaddr(g_a1l);
    __nv_bfloat16* a2h = (__nv_bfloat16*)symaddr(g_a2h);
    __nv_bfloat16* a2l = (__nv_bfloat16*)symaddr(g_a2l);
    __nv_bfloat16* ash = (__nv_bfloat16*)symaddr(g_ash);
    __nv_bfloat16* asl = (__nv_bfloat16*)symaddr(g_asl);
    __nv_bfloat16* h2h = (__nv_bfloat16*)symaddr(g_h2h);
    __nv_bfloat16* h2l = (__nv_bfloat16*)symaddr(g_h2l);
    __nv_bfloat16* h1th= (__nv_bfloat16*)symaddr(g_h1th);
    __nv_bfloat16* h1tl= (__nv_bfloat16*)symaddr(g_h1tl);
    __nv_bfloat16* xTh = (__nv_bfloat16*)symaddr(g_xTh);
    __nv_bfloat16* xTl = (__nv_bfloat16*)symaddr(g_xTl);
    __nv_bfloat16* mTh = (__nv_bfloat16*)symaddr(g_mTh);
    __nv_bfloat16* mTl = (__nv_bfloat16*)symaddr(g_mTl);
    __nv_bfloat16* wTh = (__nv_bfloat16*)symaddr(g_wTh);
    __nv_bfloat16* wTl = (__nv_bfloat16*)symaddr(g_wTl);
    __nv_bfloat16* x3h = (__nv_bfloat16*)symaddr(g_x3h);
    __nv_bfloat16* x3l = (__nv_bfloat16*)symaddr(g_x3l);

    cudaFuncSetAttribute(gemm_sp<0>, cudaFuncAttributeMaxDynamicSharedMemorySize, GSMEM_SZ);
    cudaFuncSetAttribute(gemm_sp<1>, cudaFuncAttributeMaxDynamicSharedMemorySize, GSMEM_SZ);

    const dim3 tb(32, 8);

    // 1) xln = LN(x; ln1) -> fp32 + split
    ln_split<<<MTOK, 256>>>(x, ln1_g, ln1_b, xf, xh, xl);

    // 2) style vectors; fused bias
    style_gemm<<<dim3((H1h/2)/32, Bb), 256>>>(w,       2*WDd, s1_W, s1_b, s1,  H1h/2);
    style_gemm<<<dim3((H1h/2)/32, Bb), 256>>>(w,       2*WDd, s2_W, s2_b, s2,  H1h/2);
    style_gemm<<<dim3((CDd/2)/32, Bb), 256>>>(w + WDd, 2*WDd, ss_W, ss_b, ssv, CDd/2);
    concat2<<<(2*H1h + 255)/256, 256>>>(g1_b, g2_b, b12, H1h);

    // 3) fused g1|g2 GEMM: h[16384][1536] = xln @ [g1_W | g2_W] + b12
    transpose_split<<<dim3(H1h/32, Cc/32, 1), tb>>>(g1_W, wTh, wTl, Cc, H1h, 0, 0);
    transpose_split<<<dim3(H1h/32, Cc/32, 1), tb>>>(g2_W, wTh + (long long)H1h*Cc,
                                                    wTl + (long long)H1h*Cc, Cc, H1h, 0, 0);
    gemm_sp<0><<<dim3(2*H1h/128, MTOK/128, 1), 256, GSMEM_SZ>>>(
        xh, xl, wTh, wTl, h, nullptr, nullptr, b12, nullptr,
        MTOK, 2*H1h, Cc, 0, 0, 0, 0);

    // 4) GLUs for both branches (fused h layout: [a1|g1t|a2|g2t] per row of 1536)
    glu_split<<<(int)(((long long)MTOK*(TDd/4) + 255)/256), 256>>>(h,        2*H1h, TDd, s1, a1h, a1l);
    glu_split<<<(int)(((long long)MTOK*(TDd/4) + 255)/256), 256>>>(h + H1h,  2*H1h, TDd, s2, a2h, a2l);

    // 5) h1 = a1 @ m1_W + m1_b (fp32); h2 = a2 @ m2_W + m2_b (split only)
    transpose_split<<<dim3(TDd/32, TDd/32, 1), tb>>>(m1_W, wTh, wTl, TDd, TDd, 0, 0);
    gemm_sp<0><<<dim3(TDd/128, MTOK/128, 1), 256, GSMEM_SZ>>>(
        a1h, a1l, wTh, wTl, h1, nullptr, nullptr, m1_b, nullptr,
        MTOK, TDd, TDd, 0, 0, 0, 0);
    transpose_split<<<dim3(TDd/32, TDd/32, 1), tb>>>(m2_W, wTh, wTl, TDd, TDd, 0, 0);
    gemm_sp<0><<<dim3(TDd/128, MTOK/128, 1), 256, GSMEM_SZ>>>(
        a2h, a2l, wTh, wTl, nullptr, h2h, h2l, m2_b, nullptr,
        MTOK, TDd, TDd, 0, 0, 0, 0);

    // 6) mix[b] = gelu(h1[b]^T @ xln[b])
    transpose_split<<<dim3(TDd/32, Tt/32, Bb), tb>>>(h1, h1th, h1tl, Tt, TDd,
        (long long)Tt*TDd, (long long)Tt*TDd);
    transpose_split<<<dim3(Cc/32, Tt/32, Bb), tb>>>(xf, xTh, xTl, Tt, Cc,
        (long long)Tt*Cc, (long long)Tt*Cc);
    gemm_sp<1><<<dim3(Cc/128, TDd/128, Bb), 256, GSMEM_SZ>>>(
        h1th, h1tl, xTh, xTl, mix, nullptr, nullptr, zb, nullptr,
        TDd, Cc, Tt, (long long)TDd*Tt, (long long)Cc*Tt, (long long)TDd*Cc, 0);

    // 7) x2[b] = xln[b] + h2[b] @ mix[b]
    transpose_split<<<dim3(Cc/32, TDd/32, Bb), tb>>>(mix, mTh, mTl, TDd, Cc,
        (long long)TDd*Cc, (long long)TDd*Cc);
    gemm_sp<0><<<dim3(Cc/128, Tt/128, Bb), 256, GSMEM_SZ>>>(
        h2h, h2l, mTh, mTl, x2, nullptr, nullptr, zb, xf,
        Tt, Cc, TDd, (long long)Tt*TDd, (long long)Cc*TDd, (long long)Tt*Cc, (long long)Tt*Cc);

    // 8) xln2 = LN(x2; ln2) -> split only (reuse xh/xl)
    ln_split<<<MTOK, 256>>>(x2, ln2_g, ln2_b, nullptr, xh, xl);

    // 9) Hs = xln2 @ gs_W + gs_b ; as = glu(Hs)*ss ; x3 = x2 + as @ ms_W + ms_b
    transpose_split<<<dim3(CDd/32, Cc/32, 1), tb>>>(gs_W, wTh, wTl, Cc, CDd, 0, 0);
    gemm_sp<0><<<dim3(CDd/128, MTOK/128, 1), 256, GSMEM_SZ>>>(
        xh, xl, wTh, wTl, h, nullptr, nullptr, gs_b, nullptr,
        MTOK, CDd, Cc, 0, 0, 0, 0);
    glu_split<<<(int)(((long long)MTOK*(CDd/8) + 255)/256), 256>>>(h, CDd, CDd/2, ssv, ash, asl);
    transpose_split<<<dim3(Cc/32, (CDd/2)/32, 1), tb>>>(ms_W, wTh, wTl, CDd/2, Cc, 0, 0);
    gemm_sp<0><<<dim3(Cc/128, MTOK/128, 1), 256, GSMEM_SZ>>>(
        ash, asl, wTh, wTl, x2, x3h, x3l, ms_b, x2,
        MTOK, Cc, CDd/2, 0, 0, 0, 0);

    // 10) head: Hr = x3 @ r1_W + r1_b ; ar = glu(Hr) ; out = ar @ r2_W + r2_b
    transpose_split<<<dim3(Cc/32, Cc/32, 1), tb>>>(r1_W, wTh, wTl, Cc, Cc, 0, 0);
    gemm_sp<0><<<dim3(Cc/128, MTOK/128, 1), 256, GSMEM_SZ>>>(
        x3h, x3l, wTh, wTl, h, nullptr, nullptr, r1_b, nullptr,
        MTOK, Cc, Cc, 0, 0, 0, 0);
    glu_split<<<(int)(((long long)MTOK*(TDd/4) + 255)/256), 256>>>(h, Cc, Cc/2, nullptr, a1h, a1l);
    transpose_split<<<dim3(Cc/32, (Cc/2)/32, 1), tb>>>(r2_W, wTh, wTl, Cc/2, Cc, 0, 0);
    gemm_sp<0><<<dim3(Cc/128, MTOK/128, 1), 256, GSMEM_SZ>>>(
        a1h, a1l, wTh, wTl, out, nullptr, nullptr, r2_b, nullptr,
        MTOK, Cc, Cc/2, 0, 0, 0, 0);
}